// round 14
// baseline (speedup 1.0000x reference)
#include <cuda_runtime.h>
#include <cuda_bf16.h>
#include <cstdint>

#define BB      32768
#define HD      256
#define MT      128              // batch rows per CTA
#define KC      64               // K elems per chunk
#define NCHUNK  8                // 512/64
#define NT      256              // threads (8 warps, 64x64 warp tiles)

// stage layout (bytes): Ah[16K] Al[16K] Bh[32K] Bl[32K]
#define AH_OFF  0
#define AL_OFF  16384
#define BH_OFF  32768
#define BL_OFF  65536
#define STAGE   98304
#define SMEM_DYN (2*STAGE + 1024)

// ---- device scratch (allocation-free rule: __device__ globals) ----
__device__ unsigned char g_Bh[3][262144];   // pre-swizzled B^T hi: [wr, wz, [whx;whh]]
__device__ unsigned char g_Bl[3][262144];   // lo parts
__device__ float g_rh[(size_t)BB * HD];     // r * h_prev
__device__ float g_z [(size_t)BB * HD];     // z gate

// ================= helpers =================
static __device__ __forceinline__ unsigned sm_u32(const void* p) {
    unsigned a;
    asm("{.reg .u64 t; cvta.to.shared.u64 t, %1; cvt.u32.u64 %0, t;}" : "=r"(a) : "l"(p));
    return a;
}
static __device__ __forceinline__ void ldsm4(unsigned* r, unsigned addr) {
    asm volatile("ldmatrix.sync.aligned.m8n8.x4.shared.b16 {%0,%1,%2,%3}, [%4];"
                 : "=r"(r[0]), "=r"(r[1]), "=r"(r[2]), "=r"(r[3]) : "r"(addr));
}
static __device__ __forceinline__ void mma16816(float* c, const unsigned* a, const unsigned* b) {
    asm volatile("mma.sync.aligned.m16n8k16.row.col.f32.bf16.bf16.f32 "
                 "{%0,%1,%2,%3}, {%4,%5,%6,%7}, {%8,%9}, {%0,%1,%2,%3};"
                 : "+f"(c[0]), "+f"(c[1]), "+f"(c[2]), "+f"(c[3])
                 : "r"(a[0]), "r"(a[1]), "r"(a[2]), "r"(a[3]), "r"(b[0]), "r"(b[1]));
}
static __device__ __forceinline__ void cpa16(unsigned dst, const void* src) {
    asm volatile("cp.async.cg.shared.global [%0], [%1], 16;" :: "r"(dst), "l"(src));
}
#define CP_COMMIT() asm volatile("cp.async.commit_group;")
#define CP_WAIT0()  asm volatile("cp.async.wait_group 0;")

static __device__ __forceinline__ unsigned pkbf(float a, float b) {
    __nv_bfloat162 t = __halves2bfloat162(__float2bfloat16(a), __float2bfloat16(b));
    return *reinterpret_cast<unsigned*>(&t);
}
static __device__ __forceinline__ float bferr(float v) {   // v - bf16(v)
    return v - __bfloat162float(__float2bfloat16(v));
}
static __device__ __forceinline__ float sig(float v) { return 1.0f / (1.0f + __expf(-v)); }

// ================= prep: transpose + split + swizzle weights =================
// Per matrix, per k-chunk c (8 chunks of 64 k): region c*32768 bytes, inside:
//   offset(n, kloc) = n*128 + ((kloc*2) ^ ((n&7)<<4))
__global__ void __launch_bounds__(64)
prep_w(const float* __restrict__ wr, const float* __restrict__ wz,
       const float* __restrict__ whx, const float* __restrict__ whh)
{
    int k = blockIdx.x, mat = blockIdx.y, n4 = threadIdx.x * 4;
    const float* row = (mat == 0) ? wr + k * HD
                     : (mat == 1) ? wz + k * HD
                     : (k < 256 ? whx + k * HD : whh + (k - 256) * HD);
    float4 v = *(const float4*)(row + n4);
    float vv[4] = {v.x, v.y, v.z, v.w};
    unsigned reg = (unsigned)(k >> 6) * 32768u;
    unsigned kb  = (unsigned)(k & 63) * 2u;
    #pragma unroll
    for (int j = 0; j < 4; j++) {
        int n = n4 + j;
        unsigned off = reg + (unsigned)n * 128u + (kb ^ (((unsigned)n & 7u) << 4));
        __nv_bfloat16 h = __float2bfloat16(vv[j]);
        *(unsigned short*)(g_Bh[mat] + off) = __bfloat16_as_ushort(h);
        *(unsigned short*)(g_Bl[mat] + off) =
            __bfloat16_as_ushort(__float2bfloat16(vv[j] - __bfloat162float(h)));
    }
}

// ================= fused GRU via mma.sync bf16 (3-pass split) =================
__global__ void __launch_bounds__(NT, 1)
gru_hmma(const float* __restrict__ x,  const float* __restrict__ hp,
         const float* __restrict__ br, const float* __restrict__ bz,
         const float* __restrict__ bh, float* __restrict__ out)
{
    extern __shared__ char dynsm[];
    unsigned raw   = sm_u32(dynsm);
    unsigned abase = (raw + 1023u) & ~1023u;
    char*    smb   = dynsm + (abase - raw);

    const int tid  = threadIdx.x;
    const int lane = tid & 31;
    const int wid  = tid >> 5;
    const int wm   = wid >> 2;              // m block (64 rows): 0..1
    const int wn   = wid & 3;               // n block (64 cols): 0..3
    const int row0 = blockIdx.x * MT;

    // ldmatrix per-lane geometry
    const int      mA0    = wm * 64 + (lane & 15);           // + mi*16
    const unsigned aklane = (unsigned)(lane >> 4) * 16u;
    const int      nB     = wn * 64 + ((lane >> 4) << 3) + (lane & 7);   // + p*16
    const unsigned bklane = (unsigned)((lane >> 3) & 1) * 16u;
    const unsigned xs     = ((unsigned)(lane & 7)) << 4;

    // epilogue geometry
    const int emr = wm * 64 + (lane >> 2);                   // + mi*16 + hf*8 (local row)
    const int enc = wn * 64 + (lane & 3) * 2;                // + nb*8

    float acc[4][8][4];

    #pragma unroll 1
    for (int pass = 0; pass < 3; pass++) {
        const float* a0 = x;
        const float* a1 = (pass == 2) ? g_rh : hp;
        const unsigned char* gBh = g_Bh[pass];
        const unsigned char* gBl = g_Bl[pass];

        #pragma unroll
        for (int mi = 0; mi < 4; mi++)
            #pragma unroll
            for (int nb = 0; nb < 8; nb++)
                #pragma unroll
                for (int q = 0; q < 4; q++) acc[mi][nb][q] = 0.0f;

        // ---- staging helpers ----
        auto stageB = [&](int c, int buf) {
            unsigned bb = abase + buf * STAGE;
            const unsigned char* sH = gBh + (size_t)c * 32768;
            const unsigned char* sL = gBl + (size_t)c * 32768;
            #pragma unroll
            for (int q = 0; q < 8; q++) {
                int i = tid + q * NT;
                cpa16(bb + BH_OFF + i * 16, sH + i * 16);
                cpa16(bb + BL_OFF + i * 16, sL + i * 16);
            }
            CP_COMMIT();
        };
        float4 pf[8];
        auto ldgA = [&](int c) {
            const float* src = (c < 4) ? a0 + (size_t)row0 * HD + c * KC
                                       : a1 + (size_t)row0 * HD + (c - 4) * KC;
            #pragma unroll
            for (int q = 0; q < 8; q++) {
                int i = tid + q * NT;
                int m = i >> 4, k4 = (i & 15) << 2;
                pf[q] = *(const float4*)(src + (size_t)m * HD + k4);
            }
        };
        auto stsA = [&](int buf) {
            #pragma unroll
            for (int q = 0; q < 8; q++) {
                int i = tid + q * NT;
                int m = i >> 4;
                unsigned kb = (unsigned)(i & 15) << 3;            // bytes
                unsigned o  = (unsigned)m * 128u + (kb ^ (((unsigned)m & 7u) << 4));
                char* base = smb + buf * STAGE;
                float4 v = pf[q];
                *(uint2*)(base + AH_OFF + o) =
                    make_uint2(pkbf(v.x, v.y), pkbf(v.z, v.w));
                *(uint2*)(base + AL_OFF + o) =
                    make_uint2(pkbf(bferr(v.x), bferr(v.y)), pkbf(bferr(v.z), bferr(v.w)));
            }
        };
        auto compute = [&](int buf) {
            unsigned bb    = abase + buf * STAGE;
            unsigned aAddr = bb + (unsigned)mA0 * 128u;
            unsigned bAddr = bb + BH_OFF + (unsigned)nB * 128u;
            #pragma unroll
            for (int ks = 0; ks < 4; ks++) {
                unsigned aoff = ((unsigned)ks * 32u + aklane) ^ xs;
                unsigned ah[4][4], al[4][4];
                #pragma unroll
                for (int mi = 0; mi < 4; mi++) {
                    ldsm4(ah[mi], aAddr + AH_OFF + (unsigned)mi * 2048u + aoff);
                    ldsm4(al[mi], aAddr + AL_OFF + (unsigned)mi * 2048u + aoff);
                }
                unsigned boff = ((unsigned)ks * 32u + bklane) ^ xs;
                #pragma unroll
                for (int p = 0; p < 4; p++) {
                    unsigned bhv[4], blv[4];
                    unsigned ba = bAddr + (unsigned)p * 2048u + boff;
                    ldsm4(bhv, ba);
                    ldsm4(blv, ba + (BL_OFF - BH_OFF));
                    // hh
                    #pragma unroll
                    for (int mi = 0; mi < 4; mi++) {
                        mma16816(acc[mi][2*p],   ah[mi], bhv);
                        mma16816(acc[mi][2*p+1], ah[mi], bhv + 2);
                    }
                    // hl
                    #pragma unroll
                    for (int mi = 0; mi < 4; mi++) {
                        mma16816(acc[mi][2*p],   ah[mi], blv);
                        mma16816(acc[mi][2*p+1], ah[mi], blv + 2);
                    }
                    // lh
                    #pragma unroll
                    for (int mi = 0; mi < 4; mi++) {
                        mma16816(acc[mi][2*p],   al[mi], bhv);
                        mma16816(acc[mi][2*p+1], al[mi], bhv + 2);
                    }
                }
            }
        };

        // ---- K pipeline: double-buffered chunks ----
        stageB(0, 0);
        ldgA(0);
        stsA(0);
        CP_WAIT0();
        __syncthreads();
        #pragma unroll 1
        for (int c = 0; c < NCHUNK; c++) {
            int buf = c & 1;
            if (c < NCHUNK - 1) { stageB(c + 1, buf ^ 1); ldgA(c + 1); }
            compute(buf);
            if (c < NCHUNK - 1) { stsA(buf ^ 1); CP_WAIT0(); }
            __syncthreads();
        }

        // ---- epilogue ----
        #pragma unroll
        for (int nb = 0; nb < 8; nb++) {
            int col = enc + nb * 8;
            float2 b2;
            if (pass == 0)      b2 = *(const float2*)&br[col];
            else if (pass == 1) b2 = *(const float2*)&bz[col];
            else                b2 = *(const float2*)&bh[col];
            #pragma unroll
            for (int mi = 0; mi < 4; mi++)
                #pragma unroll
                for (int hf = 0; hf < 2; hf++) {
                    int row = row0 + emr + mi * 16 + hf * 8;
                    size_t go = (size_t)row * HD + col;
                    float v0 = acc[mi][nb][hf * 2 + 0] + b2.x;
                    float v1 = acc[mi][nb][hf * 2 + 1] + b2.y;
                    if (pass == 0) {
                        float2 h2 = *(const float2*)(hp + go);
                        *(float2*)(g_rh + go) = make_float2(sig(v0) * h2.x, sig(v1) * h2.y);
                    } else if (pass == 1) {
                        *(float2*)(g_z + go) = make_float2(sig(v0), sig(v1));
                    } else {
                        float g0 = tanhf(v0), g1 = tanhf(v1);
                        float2 h2 = *(const float2*)(hp + go);
                        float2 z2 = *(const float2*)(g_z + go);
                        *(float2*)(out + go) = make_float2(h2.x + z2.x * (g0 - h2.x),
                                                           h2.y + z2.y * (g1 - h2.y));
                    }
                }
        }
        __syncthreads();
    }
}

// ================= launch =================
extern "C" void kernel_launch(void* const* d_in, const int* in_sizes, int n_in,
                              void* d_out, int out_size)
{
    const float* x   = (const float*)d_in[0];
    const float* hp  = (const float*)d_in[1];
    const float* wr  = (const float*)d_in[2];
    const float* wz  = (const float*)d_in[3];
    const float* whh = (const float*)d_in[4];
    const float* whx = (const float*)d_in[5];
    const float* br  = (const float*)d_in[6];
    const float* bz  = (const float*)d_in[7];
    const float* bh  = (const float*)d_in[8];

    cudaFuncSetAttribute(gru_hmma, cudaFuncAttributeMaxDynamicSharedMemorySize, SMEM_DYN);

    prep_w<<<dim3(512, 3), 64>>>(wr, wz, whx, whh);
    gru_hmma<<<BB / MT, NT, SMEM_DYN>>>(x, hp, br, bz, bh, (float*)d_out);
}

// round 15
// speedup vs baseline: 1.0320x; 1.0320x over previous
#include <cuda_runtime.h>
#include <cuda_bf16.h>
#include <cstdint>

#define BB      32768
#define HD      256
#define MT      128              // batch rows per CTA
#define KC      64               // K elems per chunk
#define NCHUNK  8                // 512/64
#define NT      512              // threads (16 warps, 32x64 warp tiles)

// stage layout (bytes): Ah[16K] Al[16K] Bh[32K] Bl[32K]
#define AH_OFF  0
#define AL_OFF  16384
#define BH_OFF  32768
#define BL_OFF  65536
#define STAGE   98304
#define SMEM_DYN (2*STAGE + 1024)

// ---- device scratch (allocation-free rule: __device__ globals) ----
__device__ unsigned char g_Bh[3][262144];        // pre-swizzled B^T hi: [wr, wz, [whx;whh]]
__device__ unsigned char g_Bl[3][262144];        // lo parts
__device__ unsigned char g_Ah[256][8][16384];    // pre-split [x|h] hi, swizzled
__device__ unsigned char g_Al[256][8][16384];    // lo
__device__ unsigned char g_RHh[256][4][16384];   // split r*h hi, swizzled
__device__ unsigned char g_RHl[256][4][16384];   // lo
__device__ float g_z[(size_t)BB * HD];           // z gate (fp32)

// ================= helpers =================
static __device__ __forceinline__ unsigned sm_u32(const void* p) {
    unsigned a;
    asm("{.reg .u64 t; cvta.to.shared.u64 t, %1; cvt.u32.u64 %0, t;}" : "=r"(a) : "l"(p));
    return a;
}
static __device__ __forceinline__ void ldsm4(unsigned* r, unsigned addr) {
    asm volatile("ldmatrix.sync.aligned.m8n8.x4.shared.b16 {%0,%1,%2,%3}, [%4];"
                 : "=r"(r[0]), "=r"(r[1]), "=r"(r[2]), "=r"(r[3]) : "r"(addr));
}
static __device__ __forceinline__ void mma16816(float* c, const unsigned* a, const unsigned* b) {
    asm volatile("mma.sync.aligned.m16n8k16.row.col.f32.bf16.bf16.f32 "
                 "{%0,%1,%2,%3}, {%4,%5,%6,%7}, {%8,%9}, {%0,%1,%2,%3};"
                 : "+f"(c[0]), "+f"(c[1]), "+f"(c[2]), "+f"(c[3])
                 : "r"(a[0]), "r"(a[1]), "r"(a[2]), "r"(a[3]), "r"(b[0]), "r"(b[1]));
}
static __device__ __forceinline__ void cpa16(unsigned dst, const void* src) {
    asm volatile("cp.async.cg.shared.global [%0], [%1], 16;" :: "r"(dst), "l"(src));
}
#define CP_COMMIT() asm volatile("cp.async.commit_group;")
#define CP_WAIT0()  asm volatile("cp.async.wait_group 0;")

static __device__ __forceinline__ unsigned pkbf(float a, float b) {
    __nv_bfloat162 t = __halves2bfloat162(__float2bfloat16(a), __float2bfloat16(b));
    return *reinterpret_cast<unsigned*>(&t);
}
static __device__ __forceinline__ float bferr(float v) {   // v - bf16(v)
    return v - __bfloat162float(__float2bfloat16(v));
}
static __device__ __forceinline__ float sig(float v) { return 1.0f / (1.0f + __expf(-v)); }

// ================= prep_w: transpose + split + swizzle weights =================
// Per matrix, per k-chunk c: region c*32768 bytes, offset(n,kloc) = n*128 + ((kloc*2)^((n&7)<<4))
__global__ void __launch_bounds__(64)
prep_w(const float* __restrict__ wr, const float* __restrict__ wz,
       const float* __restrict__ whx, const float* __restrict__ whh)
{
    int k = blockIdx.x, mat = blockIdx.y, n4 = threadIdx.x * 4;
    const float* row = (mat == 0) ? wr + k * HD
                     : (mat == 1) ? wz + k * HD
                     : (k < 256 ? whx + k * HD : whh + (k - 256) * HD);
    float4 v = *(const float4*)(row + n4);
    float vv[4] = {v.x, v.y, v.z, v.w};
    unsigned reg = (unsigned)(k >> 6) * 32768u;
    unsigned kb  = (unsigned)(k & 63) * 2u;
    #pragma unroll
    for (int j = 0; j < 4; j++) {
        int n = n4 + j;
        unsigned off = reg + (unsigned)n * 128u + (kb ^ (((unsigned)n & 7u) << 4));
        __nv_bfloat16 h = __float2bfloat16(vv[j]);
        *(unsigned short*)(g_Bh[mat] + off) = __bfloat16_as_ushort(h);
        *(unsigned short*)(g_Bl[mat] + off) =
            __bfloat16_as_ushort(__float2bfloat16(vv[j] - __bfloat162float(h)));
    }
}

// ================= prep_a: split [x|h] into swizzled bf16 hi/lo =================
__global__ void __launch_bounds__(256)
prep_a(const float* __restrict__ x, const float* __restrict__ hp)
{
    int i   = blockIdx.x * 256 + threadIdx.x;     // 4.19M threads, 4 elems each
    int row = i >> 7;                              // batch row
    int k4  = (i & 127) << 2;                      // k position (0..508)
    const float* src = (k4 < 256) ? x + (size_t)row * HD + k4
                                  : hp + (size_t)row * HD + (k4 - 256);
    float4 v = *(const float4*)src;
    int tile = row >> 7, ml = row & 127, ch = k4 >> 6, kl = k4 & 63;
    unsigned o = (unsigned)ml * 128u + (((unsigned)kl * 2u) ^ (((unsigned)ml & 7u) << 4));
    *(uint2*)(g_Ah[tile][ch] + o) = make_uint2(pkbf(v.x, v.y), pkbf(v.z, v.w));
    *(uint2*)(g_Al[tile][ch] + o) =
        make_uint2(pkbf(bferr(v.x), bferr(v.y)), pkbf(bferr(v.z), bferr(v.w)));
}

// ================= fused GRU via mma.sync bf16 (3-pass split, pure cp.async) =================
__global__ void __launch_bounds__(NT, 1)
gru_hmma(const float* __restrict__ hp, const float* __restrict__ br,
         const float* __restrict__ bz, const float* __restrict__ bh,
         float* __restrict__ out)
{
    extern __shared__ char dynsm[];
    unsigned raw   = sm_u32(dynsm);
    unsigned abase = (raw + 1023u) & ~1023u;

    const int tid  = threadIdx.x;
    const int lane = tid & 31;
    const int wid  = tid >> 5;
    const int wm   = wid & 3;               // m block (32 rows)
    const int wn   = wid >> 2;              // n block (64 cols)
    const int tile = blockIdx.x;
    const int row0 = tile * MT;

    // ldmatrix per-lane geometry
    const int      mA0    = wm * 32 + (lane & 15);
    const unsigned aklane = (unsigned)(lane >> 4) * 16u;
    const int      nB     = wn * 64 + ((lane >> 4) << 3) + (lane & 7);
    const unsigned bklane = (unsigned)((lane >> 3) & 1) * 16u;
    const unsigned xs     = ((unsigned)(lane & 7)) << 4;

    // epilogue geometry
    const int emr = wm * 32 + (lane >> 2);                   // + mi*16 + hf*8 (local row)
    const int enc = wn * 64 + (lane & 3) * 2;                // + nb*8

    float acc[2][8][4];

    #pragma unroll 1
    for (int pass = 0; pass < 3; pass++) {
        const unsigned char* gBh = g_Bh[pass];
        const unsigned char* gBl = g_Bl[pass];

        #pragma unroll
        for (int mi = 0; mi < 2; mi++)
            #pragma unroll
            for (int nb = 0; nb < 8; nb++)
                #pragma unroll
                for (int q = 0; q < 4; q++) acc[mi][nb][q] = 0.0f;

        auto stageAB = [&](int c, int buf) {
            unsigned bb = abase + buf * STAGE;
            const unsigned char *aH, *aL;
            if (pass == 2 && c >= 4) { aH = g_RHh[tile][c - 4]; aL = g_RHl[tile][c - 4]; }
            else                     { aH = g_Ah[tile][c];      aL = g_Al[tile][c]; }
            #pragma unroll
            for (int q = 0; q < 2; q++) {
                int i = tid + q * NT;
                cpa16(bb + AH_OFF + i * 16, aH + i * 16);
                cpa16(bb + AL_OFF + i * 16, aL + i * 16);
            }
            const unsigned char* sH = gBh + (size_t)c * 32768;
            const unsigned char* sL = gBl + (size_t)c * 32768;
            #pragma unroll
            for (int q = 0; q < 4; q++) {
                int i = tid + q * NT;
                cpa16(bb + BH_OFF + i * 16, sH + i * 16);
                cpa16(bb + BL_OFF + i * 16, sL + i * 16);
            }
            CP_COMMIT();
        };
        auto compute = [&](int buf) {
            unsigned bb    = abase + buf * STAGE;
            unsigned aAddr = bb + (unsigned)mA0 * 128u;
            unsigned bAddr = bb + BH_OFF + (unsigned)nB * 128u;
            #pragma unroll
            for (int ks = 0; ks < 4; ks++) {
                unsigned aoff = ((unsigned)ks * 32u + aklane) ^ xs;
                unsigned ah0[4], ah1[4], al0[4], al1[4];
                ldsm4(ah0, aAddr + AH_OFF + aoff);
                ldsm4(ah1, aAddr + AH_OFF + 2048u + aoff);
                ldsm4(al0, aAddr + AL_OFF + aoff);
                ldsm4(al1, aAddr + AL_OFF + 2048u + aoff);
                unsigned boff = ((unsigned)ks * 32u + bklane) ^ xs;
                #pragma unroll
                for (int p = 0; p < 4; p++) {
                    unsigned bhv[4], blv[4];
                    unsigned ba = bAddr + (unsigned)p * 2048u + boff;
                    ldsm4(bhv, ba);
                    ldsm4(blv, ba + (BL_OFF - BH_OFF));
                    mma16816(acc[0][2*p],   ah0, bhv);     mma16816(acc[1][2*p],   ah1, bhv);
                    mma16816(acc[0][2*p+1], ah0, bhv + 2); mma16816(acc[1][2*p+1], ah1, bhv + 2);
                    mma16816(acc[0][2*p],   ah0, blv);     mma16816(acc[1][2*p],   ah1, blv);
                    mma16816(acc[0][2*p+1], ah0, blv + 2); mma16816(acc[1][2*p+1], ah1, blv + 2);
                    mma16816(acc[0][2*p],   al0, bhv);     mma16816(acc[1][2*p],   al1, bhv);
                    mma16816(acc[0][2*p+1], al0, bhv + 2); mma16816(acc[1][2*p+1], al1, bhv + 2);
                }
            }
        };

        // ---- K pipeline: double-buffered chunks, pure cp.async ----
        stageAB(0, 0);
        CP_WAIT0();
        __syncthreads();
        #pragma unroll 1
        for (int c = 0; c < NCHUNK; c++) {
            int buf = c & 1;
            if (c < NCHUNK - 1) stageAB(c + 1, buf ^ 1);
            compute(buf);
            CP_WAIT0();
            __syncthreads();
        }

        // ---- epilogue ----
        #pragma unroll
        for (int nb = 0; nb < 8; nb++) {
            int col = enc + nb * 8;
            float2 b2;
            if (pass == 0)      b2 = *(const float2*)&br[col];
            else if (pass == 1) b2 = *(const float2*)&bz[col];
            else                b2 = *(const float2*)&bh[col];
            #pragma unroll
            for (int mi = 0; mi < 2; mi++)
                #pragma unroll
                for (int hf = 0; hf < 2; hf++) {
                    int ml  = emr + mi * 16 + hf * 8;             // local row
                    size_t go = (size_t)(row0 + ml) * HD + col;
                    float v0 = acc[mi][nb][hf * 2 + 0] + b2.x;
                    float v1 = acc[mi][nb][hf * 2 + 1] + b2.y;
                    if (pass == 0) {
                        float2 h2 = *(const float2*)(hp + go);
                        float rh0 = sig(v0) * h2.x, rh1 = sig(v1) * h2.y;
                        int cc = col >> 6, kl = col & 63;
                        unsigned o = (unsigned)ml * 128u +
                                     (((unsigned)kl * 2u) ^ (((unsigned)ml & 7u) << 4));
                        *(unsigned*)(g_RHh[tile][cc] + o) = pkbf(rh0, rh1);
                        *(unsigned*)(g_RHl[tile][cc] + o) = pkbf(bferr(rh0), bferr(rh1));
                    } else if (pass == 1) {
                        *(float2*)(g_z + go) = make_float2(sig(v0), sig(v1));
                    } else {
                        float g0 = tanhf(v0), g1 = tanhf(v1);
                        float2 h2 = *(const float2*)(hp + go);
                        float2 z2 = *(const float2*)(g_z + go);
                        *(float2*)(out + go) = make_float2(h2.x + z2.x * (g0 - h2.x),
                                                           h2.y + z2.y * (g1 - h2.y));
                    }
                }
        }
        __syncthreads();
    }
}

// ================= launch =================
extern "C" void kernel_launch(void* const* d_in, const int* in_sizes, int n_in,
                              void* d_out, int out_size)
{
    const float* x   = (const float*)d_in[0];
    const float* hp  = (const float*)d_in[1];
    const float* wr  = (const float*)d_in[2];
    const float* wz  = (const float*)d_in[3];
    const float* whh = (const float*)d_in[4];
    const float* whx = (const float*)d_in[5];
    const float* br  = (const float*)d_in[6];
    const float* bz  = (const float*)d_in[7];
    const float* bh  = (const float*)d_in[8];

    cudaFuncSetAttribute(gru_hmma, cudaFuncAttributeMaxDynamicSharedMemorySize, SMEM_DYN);

    prep_w<<<dim3(512, 3), 64>>>(wr, wz, whx, whh);
    prep_a<<<16384, 256>>>(x, hp);
    gru_hmma<<<BB / MT, NT, SMEM_DYN>>>(hp, br, bz, bh, (float*)d_out);
}

// round 17
// speedup vs baseline: 2.1471x; 2.0805x over previous
#include <cuda_runtime.h>
#include <cuda_fp16.h>
#include <cstdint>

#define BB      32768
#define HD      256
#define MT      64               // batch rows per CTA
#define KC      64               // K elems per chunk
#define NCHUNK  8                // 512/64
#define NT      256              // threads (8 warps, 32x64 warp tiles)

// stage layout (bytes): A[8K] B[32K]
#define A_OFF   0
#define B_OFF   8192
#define STAGE   40960
#define SMEM_DYN (2*STAGE + 1024)     // 82944

// ---- device scratch (allocation-free rule: __device__ globals) ----
__device__ unsigned char g_B[3][262144];        // pre-swizzled B^T fp16: [wr, wz, [whx;whh]]
__device__ unsigned char g_A[512][8][8192];     // pre-converted [x|h] fp16, swizzled, per tile/chunk
__device__ unsigned char g_RH[512][4][8192];    // r*h fp16, swizzled
__device__ float g_z[(size_t)BB * HD];          // z gate (fp32)

// ================= helpers =================
static __device__ __forceinline__ unsigned sm_u32(const void* p) {
    unsigned a;
    asm("{.reg .u64 t; cvta.to.shared.u64 t, %1; cvt.u32.u64 %0, t;}" : "=r"(a) : "l"(p));
    return a;
}
static __device__ __forceinline__ void ldsm4(unsigned* r, unsigned addr) {
    asm volatile("ldmatrix.sync.aligned.m8n8.x4.shared.b16 {%0,%1,%2,%3}, [%4];"
                 : "=r"(r[0]), "=r"(r[1]), "=r"(r[2]), "=r"(r[3]) : "r"(addr));
}
static __device__ __forceinline__ void mma16816(float* c, const unsigned* a, const unsigned* b) {
    asm volatile("mma.sync.aligned.m16n8k16.row.col.f32.f16.f16.f32 "
                 "{%0,%1,%2,%3}, {%4,%5,%6,%7}, {%8,%9}, {%0,%1,%2,%3};"
                 : "+f"(c[0]), "+f"(c[1]), "+f"(c[2]), "+f"(c[3])
                 : "r"(a[0]), "r"(a[1]), "r"(a[2]), "r"(a[3]), "r"(b[0]), "r"(b[1]));
}
static __device__ __forceinline__ void cpa16(unsigned dst, const void* src) {
    asm volatile("cp.async.cg.shared.global [%0], [%1], 16;" :: "r"(dst), "l"(src));
}
#define CP_COMMIT() asm volatile("cp.async.commit_group;")
#define CP_WAIT0()  asm volatile("cp.async.wait_group 0;")

static __device__ __forceinline__ unsigned pkhf(float a, float b) {
    __half2 t = __floats2half2_rn(a, b);
    return *reinterpret_cast<unsigned*>(&t);
}
static __device__ __forceinline__ float sig(float v) { return 1.0f / (1.0f + __expf(-v)); }

// ================= prep_w: transpose + convert + swizzle weights =================
// Per matrix, per k-chunk c: region c*32768 bytes, offset(n,kloc) = n*128 + ((kloc*2)^((n&7)<<4))
__global__ void __launch_bounds__(64)
prep_w(const float* __restrict__ wr, const float* __restrict__ wz,
       const float* __restrict__ whx, const float* __restrict__ whh)
{
    int k = blockIdx.x, mat = blockIdx.y, n4 = threadIdx.x * 4;
    const float* row = (mat == 0) ? wr + k * HD
                     : (mat == 1) ? wz + k * HD
                     : (k < 256 ? whx + k * HD : whh + (k - 256) * HD);
    float4 v = *(const float4*)(row + n4);
    float vv[4] = {v.x, v.y, v.z, v.w};
    unsigned reg = (unsigned)(k >> 6) * 32768u;
    unsigned kb  = (unsigned)(k & 63) * 2u;
    #pragma unroll
    for (int j = 0; j < 4; j++) {
        int n = n4 + j;
        unsigned off = reg + (unsigned)n * 128u + (kb ^ (((unsigned)n & 7u) << 4));
        *(unsigned short*)(g_B[mat] + off) = __half_as_ushort(__float2half_rn(vv[j]));
    }
}

// ================= prep_a: convert [x|h] into swizzled fp16 =================
__global__ void __launch_bounds__(256)
prep_a(const float* __restrict__ x, const float* __restrict__ hp)
{
    int i   = blockIdx.x * 256 + threadIdx.x;     // 4.19M threads, 4 elems each
    int row = i >> 7;                              // batch row
    int k4  = (i & 127) << 2;                      // k position (0..508)
    const float* src = (k4 < 256) ? x + (size_t)row * HD + k4
                                  : hp + (size_t)row * HD + (k4 - 256);
    float4 v = *(const float4*)src;
    int tile = row >> 6, ml = row & 63, ch = k4 >> 6, kl = k4 & 63;
    unsigned o = (unsigned)ml * 128u + (((unsigned)kl * 2u) ^ (((unsigned)ml & 7u) << 4));
    *(uint2*)(g_A[tile][ch] + o) = make_uint2(pkhf(v.x, v.y), pkhf(v.z, v.w));
}

// ================= fused GRU via mma.sync fp16 (single term), 3 passes =================
__global__ void __launch_bounds__(NT, 2)
gru_hmma(const float* __restrict__ hp, const float* __restrict__ br,
         const float* __restrict__ bz, const float* __restrict__ bh,
         float* __restrict__ out)
{
    extern __shared__ char dynsm[];
    unsigned raw   = sm_u32(dynsm);
    unsigned abase = (raw + 1023u) & ~1023u;

    const int tid  = threadIdx.x;
    const int lane = tid & 31;
    const int wid  = tid >> 5;
    const int wm   = wid >> 2;              // m block (32 rows): 0..1
    const int wn   = wid & 3;               // n block (64 cols): 0..3
    const int tile = blockIdx.x;
    const int row0 = tile * MT;

    // ldmatrix per-lane geometry
    const int      mA0    = wm * 32 + (lane & 15);                      // + mi*16
    const unsigned aklane = (unsigned)(lane >> 4) * 16u;
    const int      nB     = wn * 64 + ((lane >> 4) << 3) + (lane & 7);  // + p*16
    const unsigned bklane = (unsigned)((lane >> 3) & 1) * 16u;
    const unsigned xs     = ((unsigned)(lane & 7)) << 4;

    // epilogue geometry
    const int emr = wm * 32 + (lane >> 2);                  // + mi*16 + hf*8 (local row)
    const int enc = wn * 64 + (lane & 3) * 2;               // + nb*8

    float acc[2][8][4];

    #pragma unroll 1
    for (int pass = 0; pass < 3; pass++) {
        const unsigned char* gB = g_B[pass];

        #pragma unroll
        for (int mi = 0; mi < 2; mi++)
            #pragma unroll
            for (int nb = 0; nb < 8; nb++)
                #pragma unroll
                for (int q = 0; q < 4; q++) acc[mi][nb][q] = 0.0f;

        auto stageAB = [&](int c, int buf) {
            unsigned bb = abase + buf * STAGE;
            const unsigned char* aS;
            if (pass == 2 && c >= 4) aS = g_RH[tile][c - 4];
            else                     aS = g_A[tile][c];
            #pragma unroll
            for (int q = 0; q < 2; q++) {
                int i = tid + q * NT;
                cpa16(bb + A_OFF + i * 16, aS + i * 16);
            }
            const unsigned char* bS = gB + (size_t)c * 32768;
            #pragma unroll
            for (int q = 0; q < 8; q++) {
                int i = tid + q * NT;
                cpa16(bb + B_OFF + i * 16, bS + i * 16);
            }
            CP_COMMIT();
        };
        auto compute = [&](int buf) {
            unsigned bb    = abase + buf * STAGE;
            unsigned aAddr = bb + A_OFF + (unsigned)mA0 * 128u;
            unsigned bAddr = bb + B_OFF + (unsigned)nB * 128u;
            #pragma unroll
            for (int ks = 0; ks < 4; ks++) {
                unsigned aoff = ((unsigned)ks * 32u + aklane) ^ xs;
                unsigned a0[4], a1[4];
                ldsm4(a0, aAddr + aoff);
                ldsm4(a1, aAddr + 2048u + aoff);
                unsigned boff = ((unsigned)ks * 32u + bklane) ^ xs;
                #pragma unroll
                for (int p = 0; p < 4; p++) {
                    unsigned bv[4];
                    ldsm4(bv, bAddr + (unsigned)p * 2048u + boff);
                    mma16816(acc[0][2*p],   a0, bv);     mma16816(acc[1][2*p],   a1, bv);
                    mma16816(acc[0][2*p+1], a0, bv + 2); mma16816(acc[1][2*p+1], a1, bv + 2);
                }
            }
        };

        // ---- K pipeline: double-buffered chunks ----
        stageAB(0, 0);
        CP_WAIT0();
        __syncthreads();
        #pragma unroll 1
        for (int c = 0; c < NCHUNK; c++) {
            int buf = c & 1;
            if (c < NCHUNK - 1) stageAB(c + 1, buf ^ 1);
            compute(buf);
            CP_WAIT0();
            __syncthreads();
        }

        // ---- epilogue ----
        #pragma unroll
        for (int nb = 0; nb < 8; nb++) {
            int col = enc + nb * 8;
            float2 b2;
            if (pass == 0)      b2 = *(const float2*)&br[col];
            else if (pass == 1) b2 = *(const float2*)&bz[col];
            else                b2 = *(const float2*)&bh[col];
            #pragma unroll
            for (int mi = 0; mi < 2; mi++)
                #pragma unroll
                for (int hf = 0; hf < 2; hf++) {
                    int ml  = emr + mi * 16 + hf * 8;             // local row (0..63)
                    size_t go = (size_t)(row0 + ml) * HD + col;
                    float v0 = acc[mi][nb][hf * 2 + 0] + b2.x;
                    float v1 = acc[mi][nb][hf * 2 + 1] + b2.y;
                    if (pass == 0) {
                        float2 h2 = *(const float2*)(hp + go);
                        float rh0 = sig(v0) * h2.x, rh1 = sig(v1) * h2.y;
                        int cc = col >> 6, kl = col & 63;
                        unsigned o = (unsigned)ml * 128u +
                                     (((unsigned)kl * 2u) ^ (((unsigned)ml & 7u) << 4));
                        *(unsigned*)(g_RH[tile][cc] + o) = pkhf(rh0, rh1);
                    } else if (pass == 1) {
                        *(float2*)(g_z + go) = make_float2(sig(v0), sig(v1));
                    } else {
                        float g0 = tanhf(v0), g1 = tanhf(v1);
                        float2 h2 = *(const float2*)(hp + go);
                        float2 z2 = *(const float2*)(g_z + go);
                        *(float2*)(out + go) = make_float2(h2.x + z2.x * (g0 - h2.x),
                                                           h2.y + z2.y * (g1 - h2.y));
                    }
                }
        }
        __syncthreads();
    }
}

// ================= launch =================
extern "C" void kernel_launch(void* const* d_in, const int* in_sizes, int n_in,
                              void* d_out, int out_size)
{
    const float* x   = (const float*)d_in[0];
    const float* hp  = (const float*)d_in[1];
    const float* wr  = (const float*)d_in[2];
    const float* wz  = (const float*)d_in[3];
    const float* whh = (const float*)d_in[4];
    const float* whx = (const float*)d_in[5];
    const float* br  = (const float*)d_in[6];
    const float* bz  = (const float*)d_in[7];
    const float* bh  = (const float*)d_in[8];

    cudaFuncSetAttribute(gru_hmma, cudaFuncAttributeMaxDynamicSharedMemorySize, SMEM_DYN);

    prep_w<<<dim3(512, 3), 64>>>(wr, wz, whx, whh);
    prep_a<<<16384, 256>>>(x, hp);
    gru_hmma<<<BB / MT, NT, SMEM_DYN>>>(hp, br, bz, bh, (float*)d_out);
}